// round 11
// baseline (speedup 1.0000x reference)
#include <cuda_runtime.h>
#include <cuda_fp16.h>
#include <math.h>
#include <stdint.h>

// Problem constants
#define Bn 4
#define Tn 2048
#define Cn 1024
#define Hn 16
#define HSn 64
#define Mn (Bn * Tn)        // 8192 rows
#define FFn (4 * Cn)        // 4096

// ---------------------------------------------------------------------------
// Scratch (device globals)
// ---------------------------------------------------------------------------
__device__ float  g_x1 [8388608];     // [M, C]  LN1 output (f32, residual use)
__device__ float  g_x2 [8388608];     // [M, C]
__device__ float  g_x3 [8388608];     // [M, C]
__device__ __half g_qkvh[25165824];   // [M, 3C] q|k|v (f16)
__device__ __half g_x1h[8388608];     // [M, C]  LN1 output (f16, GEMM input)
__device__ __half g_x3h[8388608];     // [M, C]  LN2 output (f16, GEMM input)
__device__ __half g_oh [8388608];     // [M, C]  attention out (f16)
__device__ __half g_hbh[33554432];    // [M, 4C] relu FFN intermediate (f16)
__device__ __half g_wqkvT[3145728];   // [3C, C] packed+transposed Wq|Wk|Wv (f16 [N][K])
__device__ __half g_wpT[1048576];     // [C, C]   Wp^T  (f16 [N][K])
__device__ __half g_w1T[4194304];     // [4C, C]  W1^T  (f16 [N][K])
__device__ __half g_w2T[4194304];     // [C, 4C]  W2^T  (f16 [N][K])

// ---------------------------------------------------------------------------
// helpers
// ---------------------------------------------------------------------------
__device__ __forceinline__ void mma16816(float* c, uint32_t a0, uint32_t a1,
                                         uint32_t a2, uint32_t a3,
                                         uint32_t b0, uint32_t b1)
{
    asm volatile(
        "mma.sync.aligned.m16n8k16.row.col.f32.f16.f16.f32 "
        "{%0,%1,%2,%3}, {%4,%5,%6,%7}, {%8,%9}, {%0,%1,%2,%3};\n"
        : "+f"(c[0]), "+f"(c[1]), "+f"(c[2]), "+f"(c[3])
        : "r"(a0), "r"(a1), "r"(a2), "r"(a3), "r"(b0), "r"(b1));
}

__device__ __forceinline__ uint32_t packh2(float a, float b)
{
    __half2 h = __floats2half2_rn(a, b);
    return *reinterpret_cast<uint32_t*>(&h);
}

__device__ __forceinline__ void cp16(void* smem_dst, const void* gsrc)
{
    uint32_t d = (uint32_t)__cvta_generic_to_shared(smem_dst);
    asm volatile("cp.async.cg.shared.global [%0], [%1], 16;\n" :: "r"(d), "l"(gsrc));
}
#define CP_COMMIT() asm volatile("cp.async.commit_group;" ::: "memory")
#define CP_WAIT1()  asm volatile("cp.async.wait_group 1;" ::: "memory")

// ---------------------------------------------------------------------------
// LayerNorm (dual output: f32 + f16)
// ---------------------------------------------------------------------------
__global__ void ln_kernel(const float* __restrict__ x, const float* __restrict__ g,
                          const float* __restrict__ beta, float* __restrict__ y,
                          __half* __restrict__ yh)
{
    const int row = blockIdx.x;
    const int t = threadIdx.x;
    const float4 v = reinterpret_cast<const float4*>(x + (size_t)row * Cn)[t];
    float s = v.x + v.y + v.z + v.w;
    float q = v.x * v.x + v.y * v.y + v.z * v.z + v.w * v.w;
#pragma unroll
    for (int off = 16; off; off >>= 1) {
        s += __shfl_xor_sync(0xffffffffu, s, off);
        q += __shfl_xor_sync(0xffffffffu, q, off);
    }
    __shared__ float ss[8], qs[8];
    if ((t & 31) == 0) { ss[t >> 5] = s; qs[t >> 5] = q; }
    __syncthreads();
    s = 0.f; q = 0.f;
#pragma unroll
    for (int i = 0; i < 8; i++) { s += ss[i]; q += qs[i]; }
    const float mu = s * (1.0f / Cn);
    const float var = q * (1.0f / Cn) - mu * mu;
    const float rstd = rsqrtf(var + 1e-5f);
    const float4 gv = reinterpret_cast<const float4*>(g)[t];
    const float4 bv = reinterpret_cast<const float4*>(beta)[t];
    float4 o;
    o.x = (v.x - mu) * rstd * gv.x + bv.x;
    o.y = (v.y - mu) * rstd * gv.y + bv.y;
    o.z = (v.z - mu) * rstd * gv.z + bv.z;
    o.w = (v.w - mu) * rstd * gv.w + bv.w;
    reinterpret_cast<float4*>(y + (size_t)row * Cn)[t] = o;
    __half2* hp = reinterpret_cast<__half2*>(yh + (size_t)row * Cn + t * 4);
    hp[0] = __floats2half2_rn(o.x, o.y);
    hp[1] = __floats2half2_rn(o.z, o.w);
}

// ---------------------------------------------------------------------------
// Pack Wq/Wk/Wv into one TRANSPOSED fp16 [3C][C] matrix.
// ---------------------------------------------------------------------------
__global__ void pack_wqkvT_kernel(const float* __restrict__ Wq, const float* __restrict__ Wk,
                                  const float* __restrict__ Wv, __half* __restrict__ out)
{
    const int n = blockIdx.y;
    const int k = blockIdx.x * 256 + threadIdx.x;
    const int which = n >> 10;
    const int jj = n & 1023;
    const int h = jj >> 6, d = jj & 63;
    const float* W = (which == 0) ? Wq : (which == 1) ? Wk : Wv;
    out[(size_t)n * Cn + k] = __float2half(W[((size_t)h * Cn + k) * HSn + d]);
}

// ---------------------------------------------------------------------------
// Tiled transpose to fp16
// ---------------------------------------------------------------------------
__global__ void transpose_kernel(const float* __restrict__ in, __half* __restrict__ out,
                                 int R, int Cc)
{
    __shared__ float t[32][33];
    const int c0 = blockIdx.x * 32, r0 = blockIdx.y * 32;
    const int x = threadIdx.x, y = threadIdx.y;
#pragma unroll
    for (int i = 0; i < 32; i += 8)
        t[y + i][x] = in[(size_t)(r0 + y + i) * Cc + c0 + x];
    __syncthreads();
#pragma unroll
    for (int i = 0; i < 32; i += 8)
        out[(size_t)(c0 + y + i) * R + r0 + x] = __float2half(t[x][y + i]);
}

// ---------------------------------------------------------------------------
// fp16 tensor-core GEMM, 3-stage cp.async pipeline.
// Block tile 128x256x32, 8 warps (2x4), warp tile 64x64, mma.sync.m16n8k16.
// Smem rows padded to 40 halfs (conflict-free 32-bit fragment loads).
// Requires M%128==0, N%256==0, K%32==0, nk>=3.
// ---------------------------------------------------------------------------
#define ASTG 5120            // A stage halfs (128*40)
#define BSTG 10240           // B stage halfs (256*40)
#define STG  (ASTG + BSTG)   // 15360 halfs = 30720 B per stage

template <bool BIAS, bool RES, bool RELU, bool OUTH>
__global__ __launch_bounds__(256, 1) void hgemm_kernel(
    const __half* __restrict__ A, const __half* __restrict__ Bt,
    const float* __restrict__ bias, const float* __restrict__ res,
    float* __restrict__ C, __half* __restrict__ Ch,
    int Mdim, int Ndim, int Kdim)
{
    extern __shared__ __half sm_h[];   // 3 stages x (A 5120 + B 10240) halfs

    const int tid  = threadIdx.x;
    const int lane = tid & 31;
    const int wid  = tid >> 5;
    const int warp_m = wid >> 2;       // 0..1 (64 rows)
    const int warp_n = wid & 3;        // 0..3 (64 cols)
    const int m0 = blockIdx.y * 128;
    const int n0 = blockIdx.x * 256;

    const int r0c = tid >> 2;          // 0..63
    const int ch  = (tid & 3) * 8;     // 0,8,16,24 (halfs)

    const __half* Ag = A  + (size_t)m0 * Kdim + ch;
    const __half* Bg = Bt + (size_t)n0 * Kdim + ch;

    auto load_stage = [&](int kt, int s) {
        __half* Ab = sm_h + s * STG;
        __half* Bb = Ab + ASTG;
        const size_t kb = (size_t)kt * 32;
        cp16(Ab + (r0c)       * 40 + ch, Ag + (size_t)(r0c)       * Kdim + kb);
        cp16(Ab + (r0c + 64)  * 40 + ch, Ag + (size_t)(r0c + 64)  * Kdim + kb);
        cp16(Bb + (r0c)       * 40 + ch, Bg + (size_t)(r0c)       * Kdim + kb);
        cp16(Bb + (r0c + 64)  * 40 + ch, Bg + (size_t)(r0c + 64)  * Kdim + kb);
        cp16(Bb + (r0c + 128) * 40 + ch, Bg + (size_t)(r0c + 128) * Kdim + kb);
        cp16(Bb + (r0c + 192) * 40 + ch, Bg + (size_t)(r0c + 192) * Kdim + kb);
    };

    float acc[4][8][4];
#pragma unroll
    for (int i = 0; i < 4; i++)
#pragma unroll
        for (int j = 0; j < 8; j++)
#pragma unroll
            for (int r = 0; r < 4; r++) acc[i][j][r] = 0.f;

    const int nk = Kdim / 32;

    load_stage(0, 0); CP_COMMIT();
    load_stage(1, 1); CP_COMMIT();

    const int g  = lane >> 2;
    const int t4 = lane & 3;

    int stage = 0;
    for (int kt = 0; kt < nk; kt++) {
        CP_WAIT1();
        __syncthreads();

        if (kt + 2 < nk) load_stage(kt + 2, (kt + 2) % 3);
        CP_COMMIT();

        const __half* As = sm_h + stage * STG;
        const __half* Bs = As + ASTG;
#pragma unroll
        for (int ks = 0; ks < 2; ks++) {
            const int kb = ks * 16 + t4 * 2;
            uint32_t a[4][4], b[8][2];
#pragma unroll
            for (int i = 0; i < 4; i++) {
                const int rA = warp_m * 64 + i * 16 + g;
                a[i][0] = *reinterpret_cast<const uint32_t*>(As + (rA)     * 40 + kb);
                a[i][1] = *reinterpret_cast<const uint32_t*>(As + (rA + 8) * 40 + kb);
                a[i][2] = *reinterpret_cast<const uint32_t*>(As + (rA)     * 40 + kb + 8);
                a[i][3] = *reinterpret_cast<const uint32_t*>(As + (rA + 8) * 40 + kb + 8);
            }
#pragma unroll
            for (int j = 0; j < 8; j++) {
                const int nB = warp_n * 64 + j * 8 + g;
                b[j][0] = *reinterpret_cast<const uint32_t*>(Bs + nB * 40 + kb);
                b[j][1] = *reinterpret_cast<const uint32_t*>(Bs + nB * 40 + kb + 8);
            }
#pragma unroll
            for (int i = 0; i < 4; i++)
#pragma unroll
                for (int j = 0; j < 8; j++)
                    mma16816(acc[i][j], a[i][0], a[i][1], a[i][2], a[i][3], b[j][0], b[j][1]);
        }
        stage = (stage + 1 == 3) ? 0 : stage + 1;
    }

    // ---- epilogue ----
#pragma unroll
    for (int i = 0; i < 4; i++) {
#pragma unroll
        for (int j = 0; j < 8; j++) {
            const int col = n0 + warp_n * 64 + j * 8 + t4 * 2;
            float2 bb = {0.f, 0.f};
            if (BIAS) bb = *reinterpret_cast<const float2*>(bias + col);
#pragma unroll
            for (int half = 0; half < 2; half++) {
                const int row = m0 + warp_m * 64 + i * 16 + g + half * 8;
                float2 v;
                v.x = acc[i][j][half * 2 + 0];
                v.y = acc[i][j][half * 2 + 1];
                if (BIAS) { v.x += bb.x; v.y += bb.y; }
                if (RES) {
                    const float2 rr = *reinterpret_cast<const float2*>(res + (size_t)row * Ndim + col);
                    v.x += rr.x; v.y += rr.y;
                }
                if (RELU) { v.x = fmaxf(v.x, 0.f); v.y = fmaxf(v.y, 0.f); }
                if (OUTH) {
                    *reinterpret_cast<__half2*>(Ch + (size_t)row * Ndim + col) =
                        __floats2half2_rn(v.x, v.y);
                } else {
                    *reinterpret_cast<float2*>(C + (size_t)row * Ndim + col) = v;
                }
            }
        }
    }
}

// ---------------------------------------------------------------------------
// Tensor-core causal flash attention (fp16 MMA, fp32 softmax/acc). Unchanged.
// ---------------------------------------------------------------------------
#define FSTR 88   // smem row stride (halfs)

__global__ __launch_bounds__(256) void flash_h_kernel(const __half* __restrict__ qkv,
                                                      __half* __restrict__ o)
{
    __shared__ __half Qs[128 * FSTR];
    __shared__ __half Ks[64 * FSTR];
    __shared__ __half Vt[64 * FSTR];

    const int tid  = threadIdx.x;
    const int lane = tid & 31;
    const int w    = tid >> 5;
    const int g    = lane >> 2;
    const int t4   = lane & 3;

    const int qi = (int)gridDim.x - 1 - (int)blockIdx.x;
    const int h  = blockIdx.y, b = blockIdx.z;
    const int q0 = qi * 128;

    const __half* Qg = qkv + ((size_t)(b * Tn + q0)) * 3072 + h * 64;
    const __half* Kg = qkv + ((size_t)(b * Tn)) * 3072 + 1024 + h * 64;
    const __half* Vg = Kg + 1024;

#pragma unroll
    for (int u = 0; u < 4; u++) {
        const int slot = tid + 256 * u;
        const int r = slot >> 3, c8 = (slot & 7) * 8;
        *reinterpret_cast<uint4*>(Qs + r * FSTR + c8) =
            *reinterpret_cast<const uint4*>(Qg + (size_t)r * 3072 + c8);
    }
    __syncthreads();

    uint32_t qa[4][4];
#pragma unroll
    for (int ks = 0; ks < 4; ks++) {
        const int base = (w * 16 + g) * FSTR + ks * 16 + 2 * t4;
        qa[ks][0] = *reinterpret_cast<const uint32_t*>(Qs + base);
        qa[ks][1] = *reinterpret_cast<const uint32_t*>(Qs + base + 8 * FSTR);
        qa[ks][2] = *reinterpret_cast<const uint32_t*>(Qs + base + 8);
        qa[ks][3] = *reinterpret_cast<const uint32_t*>(Qs + base + 8 * FSTR + 8);
    }

    float oacc[8][4];
#pragma unroll
    for (int j = 0; j < 8; j++)
#pragma unroll
        for (int r = 0; r < 4; r++) oacc[j][r] = 0.f;
    float mrow[2] = {-1e30f, -1e30f};
    float lrow[2] = {0.f, 0.f};

    const int qrow0 = q0 + w * 16 + g;
    const int qrow1 = qrow0 + 8;
    const int ntiles = 2 * qi + 2;

    for (int jt = 0; jt < ntiles; jt++) {
        const int j0 = jt * 64;
        __syncthreads();
#pragma unroll
        for (int u = 0; u < 2; u++) {
            const int slot = tid + 256 * u;
            const int r = slot >> 3, c8 = (slot & 7) * 8;
            *reinterpret_cast<uint4*>(Ks + r * FSTR + c8) =
                *reinterpret_cast<const uint4*>(Kg + (size_t)(j0 + r) * 3072 + c8);
            const uint4 vv = *reinterpret_cast<const uint4*>(Vg + (size_t)(j0 + r) * 3072 + c8);
            const __half* vh = reinterpret_cast<const __half*>(&vv);
            const int keysw = r ^ c8;
#pragma unroll
            for (int i = 0; i < 8; i++)
                Vt[(c8 + i) * FSTR + keysw] = vh[i];
        }
        __syncthreads();

        float sacc[8][4];
#pragma unroll
        for (int j = 0; j < 8; j++)
#pragma unroll
            for (int r = 0; r < 4; r++) sacc[j][r] = 0.f;
#pragma unroll
        for (int ks = 0; ks < 4; ks++) {
            const int kb = ks * 16 + 2 * t4;
#pragma unroll
            for (int j = 0; j < 8; j++) {
                const int row = (j * 8 + g) * FSTR + kb;
                const uint32_t b0 = *reinterpret_cast<const uint32_t*>(Ks + row);
                const uint32_t b1 = *reinterpret_cast<const uint32_t*>(Ks + row + 8);
                mma16816(sacc[j], qa[ks][0], qa[ks][1], qa[ks][2], qa[ks][3], b0, b1);
            }
        }

        const bool need_mask = (j0 + 63) > (q0 + w * 16);
#pragma unroll
        for (int j = 0; j < 8; j++) {
            const int c0 = j0 + j * 8 + 2 * t4;
            sacc[j][0] *= 0.03125f; sacc[j][1] *= 0.03125f;
            sacc[j][2] *= 0.03125f; sacc[j][3] *= 0.03125f;
            if (need_mask) {
                if (c0     > qrow0) sacc[j][0] = -1e30f;
                if (c0 + 1 > qrow0) sacc[j][1] = -1e30f;
                if (c0     > qrow1) sacc[j][2] = -1e30f;
                if (c0 + 1 > qrow1) sacc[j][3] = -1e30f;
            }
        }

#pragma unroll
        for (int r = 0; r < 2; r++) {
            float tmax = -1e30f;
#pragma unroll
            for (int j = 0; j < 8; j++)
                tmax = fmaxf(tmax, fmaxf(sacc[j][2 * r], sacc[j][2 * r + 1]));
            tmax = fmaxf(tmax, __shfl_xor_sync(0xffffffffu, tmax, 1));
            tmax = fmaxf(tmax, __shfl_xor_sync(0xffffffffu, tmax, 2));
            const float mn = fmaxf(mrow[r], tmax);
            const float corr = __expf(mrow[r] - mn);
            float rs = 0.f;
#pragma unroll
            for (int j = 0; j < 8; j++) {
                const float p0 = __expf(sacc[j][2 * r]     - mn);
                const float p1 = __expf(sacc[j][2 * r + 1] - mn);
                sacc[j][2 * r] = p0; sacc[j][2 * r + 1] = p1;
                rs += p0 + p1;
            }
            rs += __shfl_xor_sync(0xffffffffu, rs, 1);
            rs += __shfl_xor_sync(0xffffffffu, rs, 2);
            lrow[r] = lrow[r] * corr + rs;
            mrow[r] = mn;
#pragma unroll
            for (int j = 0; j < 8; j++) {
                oacc[j][2 * r]     *= corr;
                oacc[j][2 * r + 1] *= corr;
            }
        }

        uint32_t pa[4][4];
#pragma unroll
        for (int s = 0; s < 4; s++) {
            pa[s][0] = packh2(sacc[2 * s][0],     sacc[2 * s][1]);
            pa[s][1] = packh2(sacc[2 * s][2],     sacc[2 * s][3]);
            pa[s][2] = packh2(sacc[2 * s + 1][0], sacc[2 * s + 1][1]);
            pa[s][3] = packh2(sacc[2 * s + 1][2], sacc[2 * s + 1][3]);
        }

#pragma unroll
        for (int s = 0; s < 4; s++) {
#pragma unroll
            for (int j = 0; j < 8; j++) {
                const int drow = (j * 8 + g) * FSTR;
                const int k0 = (s * 16 + 2 * t4) ^ (j * 8);
                const int k1 = (s * 16 + 8 + 2 * t4) ^ (j * 8);
                const uint32_t b0 = *reinterpret_cast<const uint32_t*>(Vt + drow + k0);
                const uint32_t b1 = *reinterpret_cast<const uint32_t*>(Vt + drow + k1);
                mma16816(oacc[j], pa[s][0], pa[s][1], pa[s][2], pa[s][3], b0, b1);
            }
        }
    }

    const float inv0 = 1.0f / lrow[0];
    const float inv1 = 1.0f / lrow[1];
    __half* Og = o + ((size_t)(b * Tn + q0 + w * 16 + g)) * Cn + h * 64;
#pragma unroll
    for (int j = 0; j < 8; j++) {
        const int dc = j * 8 + 2 * t4;
        *reinterpret_cast<__half2*>(Og + dc) =
            __floats2half2_rn(oacc[j][0] * inv0, oacc[j][1] * inv0);
        *reinterpret_cast<__half2*>(Og + 8 * (size_t)Cn + dc) =
            __floats2half2_rn(oacc[j][2] * inv1, oacc[j][3] * inv1);
    }
}

// ---------------------------------------------------------------------------
// Launch sequence
// ---------------------------------------------------------------------------
extern "C" void kernel_launch(void* const* d_in, const int* in_sizes, int n_in,
                              void* d_out, int out_size)
{
    const float* x   = (const float*)d_in[0];
    const float* Wq  = (const float*)d_in[1];
    const float* Wk  = (const float*)d_in[2];
    const float* Wv  = (const float*)d_in[3];
    const float* Wp  = (const float*)d_in[4];
    const float* bp  = (const float*)d_in[5];
    const float* W1  = (const float*)d_in[6];
    const float* b1  = (const float*)d_in[7];
    const float* W2  = (const float*)d_in[8];
    const float* b2  = (const float*)d_in[9];
    const float* g1  = (const float*)d_in[10];
    const float* be1 = (const float*)d_in[11];
    const float* g2  = (const float*)d_in[12];
    const float* be2 = (const float*)d_in[13];
    float* out = (float*)d_out;

    float *x1, *x2, *x3;
    __half *qkvh, *x1h, *x3h, *oh, *hbh, *wqkvT, *wpT, *w1T, *w2T;
    cudaGetSymbolAddress((void**)&x1,    g_x1);
    cudaGetSymbolAddress((void**)&x2,    g_x2);
    cudaGetSymbolAddress((void**)&x3,    g_x3);
    cudaGetSymbolAddress((void**)&qkvh,  g_qkvh);
    cudaGetSymbolAddress((void**)&x1h,   g_x1h);
    cudaGetSymbolAddress((void**)&x3h,   g_x3h);
    cudaGetSymbolAddress((void**)&oh,    g_oh);
    cudaGetSymbolAddress((void**)&hbh,   g_hbh);
    cudaGetSymbolAddress((void**)&wqkvT, g_wqkvT);
    cudaGetSymbolAddress((void**)&wpT,   g_wpT);
    cudaGetSymbolAddress((void**)&w1T,   g_w1T);
    cudaGetSymbolAddress((void**)&w2T,   g_w2T);

    constexpr int GEMM_SMEM = 3 * STG * 2;  // 92160 B (3 stages x (A+B))
    cudaFuncSetAttribute(hgemm_kernel<false, false, false, true >, cudaFuncAttributeMaxDynamicSharedMemorySize, GEMM_SMEM);
    cudaFuncSetAttribute(hgemm_kernel<true,  true,  false, false>, cudaFuncAttributeMaxDynamicSharedMemorySize, GEMM_SMEM);
    cudaFuncSetAttribute(hgemm_kernel<true,  false, true,  true >, cudaFuncAttributeMaxDynamicSharedMemorySize, GEMM_SMEM);

    // 1. LN1 (dual f32/f16)
    ln_kernel<<<Mn, 256>>>(x, g1, be1, x1, x1h);
    // 2. weight prep (fp16 [N][K] layouts)
    pack_wqkvT_kernel<<<dim3(4, 3072), 256>>>(Wq, Wk, Wv, wqkvT);
    transpose_kernel<<<dim3(32, 32),  dim3(32, 8)>>>(Wp, wpT, Cn, Cn);
    transpose_kernel<<<dim3(128, 32), dim3(32, 8)>>>(W1, w1T, Cn, FFn);
    transpose_kernel<<<dim3(32, 128), dim3(32, 8)>>>(W2, w2T, FFn, Cn);
    // 3. QKV GEMM -> qkv f16   [8192,1024]@[1024,3072], grid (3072/256, 8192/128)
    hgemm_kernel<false, false, false, true><<<dim3(12, 64), 256, GEMM_SMEM>>>(
        x1h, wqkvT, nullptr, nullptr, nullptr, qkvh, Mn, 3 * Cn, Cn);
    // 4. tensor-core causal flash attention -> o f16
    flash_h_kernel<<<dim3(16, Hn, Bn), 256>>>(qkvh, oh);
    // 5. proj + bias + residual(x1): x2 = x1 + o@Wp + bp   grid (4, 64)
    hgemm_kernel<true, true, false, false><<<dim3(4, 64), 256, GEMM_SMEM>>>(
        oh, wpT, bp, x1, x2, nullptr, Mn, Cn, Cn);
    // 6. LN2 (dual)
    ln_kernel<<<Mn, 256>>>(x2, g2, be2, x3, x3h);
    // 7. FFN up + relu -> hb f16   grid (16, 64)
    hgemm_kernel<true, false, true, true><<<dim3(16, 64), 256, GEMM_SMEM>>>(
        x3h, w1T, b1, nullptr, nullptr, hbh, Mn, FFn, Cn);
    // 8. FFN down + bias + residual(x3): out = x3 + hb@W2 + b2   grid (4, 64)
    hgemm_kernel<true, true, false, false><<<dim3(4, 64), 256, GEMM_SMEM>>>(
        hbh, w2T, b2, x3, out, nullptr, Mn, Cn, FFn);
}